// round 6
// baseline (speedup 1.0000x reference)
#include <cuda_runtime.h>
#include <cstdint>

#define N_NODES 100000
#define N_EDGES 300000
#define HID 32

// Scratch (device globals; no allocation allowed)
__device__ float g_agg1[N_NODES * HID];   // layer1 edge-sum accumulator (memset to 0)
__device__ float g_uvw[N_NODES * 96];     // interleaved per-node rows: [u(32) | v(32) | w(32)]
__device__ float g_agg2[N_NODES * HID];   // layer2 accumulator (init h1@root2+bias2 by k3)

__device__ __forceinline__ void red_add_v4(float* addr, float a, float b, float c, float d) {
    asm volatile("red.global.add.v4.f32 [%0], {%1,%2,%3,%4};"
                 :: "l"(addr), "f"(a), "f"(b), "f"(c), "f"(d) : "memory");
}

// ---------------------------------------------------------------------------
// K2: layer-1 edge messages. 2 edges per thread (even/odd pair), 4 channels.
// ---------------------------------------------------------------------------
__global__ void k2_edges1(const int* __restrict__ ei,
                          const float* __restrict__ ea,
                          const float* __restrict__ nn1_w,
                          const float* __restrict__ nn1_b,
                          const float* __restrict__ x) {
    int t = blockIdx.x * blockDim.x + threadIdx.x;
    if (t >= N_EDGES * 4) return;
    int e = (t >> 3) * 2;                 // even edge of the pair
    int q = (t & 7) * 4;                  // channel base 0..28
    int2   ss  = *reinterpret_cast<const int2*>(&ei[e]);
    int2   dd  = *reinterpret_cast<const int2*>(&ei[N_EDGES + e]);
    float4 eav = *reinterpret_cast<const float4*>(&ea[2 * e]);
    float2 xa  = *reinterpret_cast<const float2*>(&x[ss.x * 2]);
    float2 xb  = *reinterpret_cast<const float2*>(&x[ss.y * 2]);

    float m0[4], m1[4];
#pragma unroll
    for (int c = 0; c < 4; c++) {
        int ch = q + c, ch2 = ch + HID;
        float wA0 = nn1_w[2 * ch + 0],  wA1 = nn1_w[2 * ch + 1],  bA = nn1_b[ch];
        float wB0 = nn1_w[2 * ch2 + 0], wB1 = nn1_w[2 * ch2 + 1], bB = nn1_b[ch2];
        float w0a = fmaf(wA0, eav.x, fmaf(wA1, eav.y, bA));
        float w1a = fmaf(wB0, eav.x, fmaf(wB1, eav.y, bB));
        m0[c] = fmaf(xa.x, w0a, xa.y * w1a);
        float w0b = fmaf(wA0, eav.z, fmaf(wA1, eav.w, bA));
        float w1b = fmaf(wB0, eav.z, fmaf(wB1, eav.w, bB));
        m1[c] = fmaf(xb.x, w0b, xb.y * w1b);
    }
    red_add_v4(&g_agg1[dd.x * HID + q], m0[0], m0[1], m0[2], m0[3]);
    red_add_v4(&g_agg1[dd.y * HID + q], m1[0], m1[1], m1[2], m1[3]);
}

// ---------------------------------------------------------------------------
// K3: per-node precompute for layer 2 (k1 folded in).
//   h1 = relu(agg1_edges + x@root1 + bias1)
//   uvw row = [h1@A | h1@B | h1@C]; agg2 = h1@root2 + bias2
// 64 nodes per block = 2 tiles of 32; weights staged ONCE per block
// (halves the 51MB of per-block weight staging traffic vs 32-node blocks).
// ---------------------------------------------------------------------------
__global__ void k3_node2(const float* __restrict__ x,
                         const float* __restrict__ root1,
                         const float* __restrict__ bias1,
                         const float* __restrict__ nn2_w,
                         const float* __restrict__ nn2_b,
                         const float* __restrict__ root2,
                         const float* __restrict__ bias2) {
    __shared__ float sA[1024], sB[1024], sC[1024], sR[1024], sH[32 * HID];
    __shared__ float sR1[64], sB1[32];
    int tid = threadIdx.x;
    for (int k = tid; k < 1024; k += 256) {
        sA[k] = nn2_w[2 * k + 0];
        sB[k] = nn2_w[2 * k + 1];
        sC[k] = nn2_b[k];
        sR[k] = root2[k];
    }
    if (tid < 64) sR1[tid] = root1[tid];
    if (tid < 32) sB1[tid] = bias1[tid];

    int warp = tid >> 5, o = tid & 31;
    int nb = warp * 4;

#pragma unroll
    for (int tile = 0; tile < 2; tile++) {
        int nodeBase = blockIdx.x * 64 + tile * 32;
        __syncthreads();   // weights ready (iter 0) / previous tile compute done
        for (int k = tid; k < 32 * HID; k += 256) {
            int n = nodeBase + (k >> 5), oo = k & 31;
            float val = 0.0f;
            if (n < N_NODES) {
                float2 xv = *reinterpret_cast<const float2*>(&x[n * 2]);
                float root = fmaf(xv.x, sR1[oo], fmaf(xv.y, sR1[HID + oo], sB1[oo]));
                val = fmaxf(g_agg1[n * HID + oo] + root, 0.0f);
            }
            sH[k] = val;
        }
        __syncthreads();

        float u[4] = {0, 0, 0, 0}, v[4] = {0, 0, 0, 0}, w[4] = {0, 0, 0, 0}, r[4] = {0, 0, 0, 0};
#pragma unroll
        for (int i = 0; i < HID; i++) {
            float wa = sA[i * HID + o];
            float wb = sB[i * HID + o];
            float wc = sC[i * HID + o];
            float wr = sR[i * HID + o];
#pragma unroll
            for (int j = 0; j < 4; j++) {
                float h = sH[(nb + j) * HID + i];
                u[j] = fmaf(h, wa, u[j]);
                v[j] = fmaf(h, wb, v[j]);
                w[j] = fmaf(h, wc, w[j]);
                r[j] = fmaf(h, wr, r[j]);
            }
        }
        float b2 = bias2[o];
#pragma unroll
        for (int j = 0; j < 4; j++) {
            int n = nodeBase + nb + j;
            if (n < N_NODES) {
                g_uvw[n * 96 + o]      = u[j];
                g_uvw[n * 96 + 32 + o] = v[j];
                g_uvw[n * 96 + 64 + o] = w[j];
                g_agg2[n * HID + o]    = r[j] + b2;
            }
        }
    }
}

// ---------------------------------------------------------------------------
// K4: layer-2 edge messages. 2 edges per thread, 4 channels (float4) each.
// ---------------------------------------------------------------------------
__global__ void k4_edges2(const int* __restrict__ ei,
                          const float* __restrict__ ea) {
    int t = blockIdx.x * blockDim.x + threadIdx.x;
    if (t >= N_EDGES * 4) return;
    int e = (t >> 3) * 2;
    int q = (t & 7) * 4;
    int2   ss  = *reinterpret_cast<const int2*>(&ei[e]);
    int2   dd  = *reinterpret_cast<const int2*>(&ei[N_EDGES + e]);
    float4 eav = *reinterpret_cast<const float4*>(&ea[2 * e]);

    const float* ba = g_uvw + ss.x * 96;
    const float* bb = g_uvw + ss.y * 96;
    float4 u0 = *reinterpret_cast<const float4*>(ba + q);
    float4 v0 = *reinterpret_cast<const float4*>(ba + 32 + q);
    float4 w0 = *reinterpret_cast<const float4*>(ba + 64 + q);
    float4 u1 = *reinterpret_cast<const float4*>(bb + q);
    float4 v1 = *reinterpret_cast<const float4*>(bb + 32 + q);
    float4 w1 = *reinterpret_cast<const float4*>(bb + 64 + q);

    float a0 = fmaf(eav.x, u0.x, fmaf(eav.y, v0.x, w0.x));
    float a1 = fmaf(eav.x, u0.y, fmaf(eav.y, v0.y, w0.y));
    float a2 = fmaf(eav.x, u0.z, fmaf(eav.y, v0.z, w0.z));
    float a3 = fmaf(eav.x, u0.w, fmaf(eav.y, v0.w, w0.w));
    red_add_v4(&g_agg2[dd.x * HID + q], a0, a1, a2, a3);

    float b0 = fmaf(eav.z, u1.x, fmaf(eav.w, v1.x, w1.x));
    float b1 = fmaf(eav.z, u1.y, fmaf(eav.w, v1.y, w1.y));
    float b2 = fmaf(eav.z, u1.z, fmaf(eav.w, v1.z, w1.z));
    float b3 = fmaf(eav.z, u1.w, fmaf(eav.w, v1.w, w1.w));
    red_add_v4(&g_agg2[dd.y * HID + q], b0, b1, b2, b3);
}

// ---------------------------------------------------------------------------
// K5: epilogue, thread-per-node. 128 nodes / 128 threads per block
// (smem 45KB -> 23KB -> ~2x occupancy, grid 391 -> 782).
// ---------------------------------------------------------------------------
#define K5_NODES 128
#define K5_THREADS 128
__global__ void k5_final(const float* __restrict__ fc1_w,
                         const float* __restrict__ fc1_b,
                         const float* __restrict__ fc2_w,
                         const float* __restrict__ fc2_b,
                         float* __restrict__ out) {
    __shared__ float sW[HID * HID];        // fc1_w, row-major (as-is)
    __shared__ float sb[HID];
    __shared__ float sf2[HID];
    __shared__ float sH[K5_NODES * 36];    // padded h2 rows
    int tid = threadIdx.x;
    for (int k = tid; k < HID * HID; k += K5_THREADS) sW[k] = fc1_w[k];   // coalesced
    if (tid < HID) { sb[tid] = fc1_b[tid]; sf2[tid] = fc2_w[tid]; }

    int base = blockIdx.x * K5_NODES;
    for (int k = tid; k < K5_NODES * HID; k += K5_THREADS) {
        int nl = k >> 5, i = k & 31;
        int n = base + nl;
        float v = 0.0f;
        if (n < N_NODES) v = fmaxf(g_agg2[n * HID + i], 0.0f);     // coalesced
        sH[nl * 36 + i] = v;                                        // conflict-free
    }
    __syncthreads();

    float4 h4[8];
    const float4* hp = reinterpret_cast<const float4*>(&sH[tid * 36]);
#pragma unroll
    for (int i = 0; i < 8; i++) h4[i] = hp[i];

    const float4* w4 = reinterpret_cast<const float4*>(sW);
    float total = 0.0f;
#pragma unroll 4
    for (int o = 0; o < HID; o++) {
        float a0 = sb[o], a1 = 0.0f, a2 = 0.0f, a3 = 0.0f;
#pragma unroll
        for (int i = 0; i < 8; i++) {
            float4 w = w4[o * 8 + i];   // broadcast LDS.128
            a0 = fmaf(h4[i].x, w.x, a0);
            a1 = fmaf(h4[i].y, w.y, a1);
            a2 = fmaf(h4[i].z, w.z, a2);
            a3 = fmaf(h4[i].w, w.w, a3);
        }
        float acc = (a0 + a1) + (a2 + a3);
        total = fmaf(fmaxf(acc, 0.0f), sf2[o], total);
    }
    int n = base + tid;
    if (n < N_NODES) out[n] = total + fc2_b[0];
}

// ---------------------------------------------------------------------------
extern "C" void kernel_launch(void* const* d_in, const int* in_sizes, int n_in,
                              void* d_out, int out_size) {
    const float* x       = (const float*)d_in[0];
    const int*   ei      = (const int*)  d_in[1];
    const float* ea      = (const float*)d_in[2];
    const float* nn1_w   = (const float*)d_in[3];
    const float* nn1_b   = (const float*)d_in[4];
    const float* root1   = (const float*)d_in[5];
    const float* bias1   = (const float*)d_in[6];
    const float* nn2_w   = (const float*)d_in[7];
    const float* nn2_b   = (const float*)d_in[8];
    const float* root2   = (const float*)d_in[9];
    const float* bias2   = (const float*)d_in[10];
    const float* fc1_w   = (const float*)d_in[11];
    const float* fc1_b   = (const float*)d_in[12];
    const float* fc2_w   = (const float*)d_in[13];
    const float* fc2_b   = (const float*)d_in[14];
    float* out = (float*)d_out;

    const int tpb = 256;
    int gridEdge = (N_EDGES * 4 + tpb - 1) / tpb;         // 4688
    int gridK3   = (N_NODES + 63) / 64;                   // 1563
    int gridK5   = (N_NODES + K5_NODES - 1) / K5_NODES;   // 782

    void* agg1_ptr = nullptr;
    cudaGetSymbolAddress(&agg1_ptr, g_agg1);
    cudaMemsetAsync(agg1_ptr, 0, sizeof(float) * N_NODES * HID, 0);

    k2_edges1<<<gridEdge, tpb>>>(ei, ea, nn1_w, nn1_b, x);
    k3_node2<<<gridK3, tpb>>>(x, root1, bias1, nn2_w, nn2_b, root2, bias2);
    k4_edges2<<<gridEdge, tpb>>>(ei, ea);
    k5_final<<<gridK5, K5_THREADS>>>(fc1_w, fc1_b, fc2_w, fc2_b, out);
}